// round 8
// baseline (speedup 1.0000x reference)
#include <cuda_runtime.h>

// Problem constants (from reference)
#define VOCAB      30000
#define N_PRE      20000
#define VEC_DIM    300
#define INPUT_SIZE 10000   // VOCAB - N_PRE
#define HIDDEN     256
#define OUT_DIM    556     // VEC_DIM + HIDDEN
#define N_TOKENS   4096    // 8 * 512

// One block per token, 256 threads.
//   threads 0..74 : copy vectors[t] (75 x float4 = 300 floats) or zeros
//   all 256       : out[300+h] = b[h] + (t>=N_PRE ? W[h*INPUT_SIZE + (t-N_PRE)] : 0)
__global__ __launch_bounds__(256, 8)
void encoder_kernel(const int* __restrict__ batch,
                    const float* __restrict__ vectors,
                    const float* __restrict__ W,
                    const float* __restrict__ b,
                    float* __restrict__ out)
{
    const int tok = blockIdx.x;
    const int tid = threadIdx.x;
    const int t   = batch[tok];

    float* __restrict__ out_row = out + (size_t)tok * OUT_DIM;

    // ---- part 1: pretrained vector (300 floats = 75 float4) ----
    if (tid < VEC_DIM / 4) {  // 75
        float4 v;
        if (t < N_PRE) {
            const float4* vrow = reinterpret_cast<const float4*>(vectors + (size_t)t * VEC_DIM);
            v = vrow[tid];
        } else {
            v = make_float4(0.f, 0.f, 0.f, 0.f);
        }
        reinterpret_cast<float4*>(out_row)[tid] = v;
    }

    // ---- part 2: linear on one-hot == column gather of W ----
    float acc = b[tid];
    if (t >= N_PRE) {
        const int c = t - N_PRE;
        acc += W[(size_t)tid * INPUT_SIZE + c];
    }
    out_row[VEC_DIM + tid] = acc;
}

extern "C" void kernel_launch(void* const* d_in, const int* in_sizes, int n_in,
                              void* d_out, int out_size)
{
    const int*   batch   = (const int*)  d_in[0];
    const float* vectors = (const float*)d_in[1];
    const float* W       = (const float*)d_in[2];
    const float* b       = (const float*)d_in[3];
    float*       out     = (float*)d_out;

    encoder_kernel<<<N_TOKENS, 256>>>(batch, vectors, W, b, out);
}

// round 9
// speedup vs baseline: 1.0036x; 1.0036x over previous
#include <cuda_runtime.h>

// Problem constants (from reference)
#define VOCAB      30000
#define N_PRE      20000
#define VEC_DIM    300
#define INPUT_SIZE 10000   // VOCAB - N_PRE
#define HIDDEN     256
#define OUT_DIM    556     // VEC_DIM + HIDDEN
#define N_TOKENS   4096    // 8 * 512

// One block per token, 256 threads.
//   threads 0..74 : copy vectors[t] (75 x float4 = 300 floats) or zeros
//   all 256       : out[300+h] = b[h] + (t>=N_PRE ? W[h*INPUT_SIZE + (t-N_PRE)] : 0)
__global__ __launch_bounds__(256, 8)
void encoder_kernel(const int* __restrict__ batch,
                    const float* __restrict__ vectors,
                    const float* __restrict__ W,
                    const float* __restrict__ b,
                    float* __restrict__ out)
{
    const int tok = blockIdx.x;
    const int tid = threadIdx.x;
    const int t   = batch[tok];

    float* __restrict__ out_row = out + (size_t)tok * OUT_DIM;

    // ---- part 1: pretrained vector (300 floats = 75 float4) ----
    if (tid < VEC_DIM / 4) {  // 75
        float4 v;
        if (t < N_PRE) {
            const float4* vrow = reinterpret_cast<const float4*>(vectors + (size_t)t * VEC_DIM);
            v = vrow[tid];
        } else {
            v = make_float4(0.f, 0.f, 0.f, 0.f);
        }
        reinterpret_cast<float4*>(out_row)[tid] = v;
    }

    // ---- part 2: linear on one-hot == column gather of W ----
    float acc = b[tid];
    if (t >= N_PRE) {
        const int c = t - N_PRE;
        acc += W[(size_t)tid * INPUT_SIZE + c];
    }
    out_row[VEC_DIM + tid] = acc;
}

extern "C" void kernel_launch(void* const* d_in, const int* in_sizes, int n_in,
                              void* d_out, int out_size)
{
    const int*   batch   = (const int*)  d_in[0];
    const float* vectors = (const float*)d_in[1];
    const float* W       = (const float*)d_in[2];
    const float* b       = (const float*)d_in[3];
    float*       out     = (float*)d_out;

    encoder_kernel<<<N_TOKENS, 256>>>(batch, vectors, W, b, out);
}

// round 10
// speedup vs baseline: 1.0332x; 1.0295x over previous
#include <cuda_runtime.h>

// Problem constants (from reference)
#define VOCAB      30000
#define N_PRE      20000
#define VEC_DIM    300
#define INPUT_SIZE 10000   // VOCAB - N_PRE
#define HIDDEN     256
#define OUT_DIM    556     // VEC_DIM + HIDDEN
#define N_TOKENS   4096    // 8 * 512

#define TPB_TOK    8       // tokens per block
#define VEC4       (VEC_DIM / 4)   // 75 float4 per vector row

// 512 blocks x 256 threads; each block handles 8 tokens.
// Phase 0: stage 8 batch indices through shared memory (one L2 trip total).
// Phase 1: each thread issues 8 INDEPENDENT predicated W-column loads (MLP=8),
//          then 8 stores: out[tok][300+tid] = b[tid] + W[tid*10000 + c].
// Phase 2: flat copy of 8x75 float4 vector rows (zeros for t >= N_PRE).
__global__ __launch_bounds__(256)
void encoder_kernel(const int* __restrict__ batch,
                    const float* __restrict__ vectors,
                    const float* __restrict__ W,
                    const float* __restrict__ b,
                    float* __restrict__ out)
{
    __shared__ int s_idx[TPB_TOK];

    const int tid  = threadIdx.x;
    const int tok0 = blockIdx.x * TPB_TOK;

    if (tid < TPB_TOK)
        s_idx[tid] = batch[tok0 + tid];

    const float bias = b[tid];          // independent load, overlaps with batch
    __syncthreads();

    int ts[TPB_TOK];
#pragma unroll
    for (int j = 0; j < TPB_TOK; j++)
        ts[j] = s_idx[j];

    // ---- hidden part: batched W-column gather, 8 loads in flight ----
    float w[TPB_TOK];
#pragma unroll
    for (int j = 0; j < TPB_TOK; j++) {
        const int t = ts[j];
        w[j] = (t >= N_PRE) ? W[(size_t)tid * INPUT_SIZE + (t - N_PRE)] : 0.f;
    }
#pragma unroll
    for (int j = 0; j < TPB_TOK; j++)
        out[(size_t)(tok0 + j) * OUT_DIM + VEC_DIM + tid] = bias + w[j];

    // ---- vector part: 8 tokens x 75 float4 = 600 items over 256 threads ----
#pragma unroll 3
    for (int k = tid; k < TPB_TOK * VEC4; k += 256) {
        const int j = k / VEC4;
        const int q = k - j * VEC4;
        const int t = ts[j];
        float4 v = make_float4(0.f, 0.f, 0.f, 0.f);
        if (t < N_PRE)
            v = reinterpret_cast<const float4*>(vectors + (size_t)t * VEC_DIM)[q];
        // out row base is 556 floats = 2224 B = 139 * 16 B -> float4 aligned
        reinterpret_cast<float4*>(out + (size_t)(tok0 + j) * OUT_DIM)[q] = v;
    }
}

extern "C" void kernel_launch(void* const* d_in, const int* in_sizes, int n_in,
                              void* d_out, int out_size)
{
    const int*   batch   = (const int*)  d_in[0];
    const float* vectors = (const float*)d_in[1];
    const float* W       = (const float*)d_in[2];
    const float* b       = (const float*)d_in[3];
    float*       out     = (float*)d_out;

    encoder_kernel<<<N_TOKENS / TPB_TOK, 256>>>(batch, vectors, W, b, out);
}